// round 5
// baseline (speedup 1.0000x reference)
#include <cuda_runtime.h>
#include <cstdint>

#define G_TOT   1024
#define WSZ     16
#define HDIM    16
#define B_ROWS  8192
#define GTILE   32                    // groups per CTA column tile
#define HSPLIT  8                     // threads per group along H (2 h each)
#define BLOCK   (GTILE * HSPLIT)      // 256 threads
#define CHUNK_ROWS 16
#define STAGES  2
#define ROWSTRIDE 16384               // floats per x/out row (G*16)
#define SLICE   (GTILE * WSZ)         // 512 floats per row-slice
#define STAGE_BYTES (CHUNK_ROWS * SLICE * 4)            // 32 KB
#define SMEM_BYTES  (STAGES * STAGE_BYTES)              // 64 KB
#define CHUNKS_PER_GT (B_ROWS / CHUNK_ROWS)             // 512
#define NCHUNKS_TOT   (CHUNKS_PER_GT * (G_TOT / GTILE)) // 16384

__device__ __forceinline__ unsigned long long pack2(float lo, float hi) {
    unsigned long long r;
    asm("mov.b64 %0, {%1, %2};" : "=l"(r) : "f"(lo), "f"(hi));
    return r;
}
__device__ __forceinline__ void unpack2(unsigned long long v, float& lo, float& hi) {
    asm("mov.b64 {%0, %1}, %2;" : "=f"(lo), "=f"(hi) : "l"(v));
}
// d = a * b + d  (packed f32x2 — ptxas never auto-emits FFMA2)
__device__ __forceinline__ void ffma2(unsigned long long& d,
                                      unsigned long long a, unsigned long long b) {
    asm("fma.rn.f32x2 %0, %1, %2, %0;" : "+l"(d) : "l"(a), "l"(b));
}
__device__ __forceinline__ uint32_t smem_u32(const void* p) {
    return (uint32_t)__cvta_generic_to_shared(p);
}
__device__ __forceinline__ void cp_async16(uint32_t dst, const void* src) {
    asm volatile("cp.async.cg.shared.global [%0], [%1], 16;" :: "r"(dst), "l"(src));
}

__global__ void __launch_bounds__(BLOCK, 3)
bd_kernel(const float* __restrict__ x, const float* __restrict__ W,
          float* __restrict__ out)
{
    extern __shared__ float xs[];   // 64 KB: 2 stages x 16 rows x 512 floats

    const int tid = threadIdx.x;
    const int hq  = tid & (HSPLIT - 1);
    const int gl  = tid >> 3;

    // flattened persistent split: single wave, balanced ±1 chunk
    const int c0 = (int)((long long)blockIdx.x       * NCHUNKS_TOT / gridDim.x);
    const int c1 = (int)((long long)(blockIdx.x + 1) * NCHUNKS_TOT / gridDim.x);
    const int n  = c1 - c0;

    // ---- loader: per-thread constants -> 8 immediate-offset cp.async per chunk
    const int lrl = tid >> 7;                          // base row in chunk (0/1)
    const uint32_t dst0 = smem_u32(xs) + lrl * 2048 + (tid & 127) * 16;

    int lgt  = c0 >> 9;                                // c / CHUNKS_PER_GT
    int lrow = (c0 & (CHUNKS_PER_GT - 1)) * CHUNK_ROWS;
    const float* lsrcT = x + (size_t)(lrow + lrl) * ROWSTRIDE
                           + lgt * SLICE + (tid & 127) * 4;
    int lslot = 0;

    auto issue_load = [&]() {
        const uint32_t d = dst0 + lslot * STAGE_BYTES;
#pragma unroll
        for (int j = 0; j < 8; ++j)
            cp_async16(d + j * 4096, lsrcT + (size_t)(2 * j) * ROWSTRIDE);
        asm volatile("cp.async.commit_group;");
        lrow  += CHUNK_ROWS;
        lsrcT += CHUNK_ROWS * ROWSTRIDE;
        if (lrow == B_ROWS) {                          // <=1 crossing per CTA
            lrow = 0; ++lgt;
            lsrcT = x + (size_t)lrl * ROWSTRIDE + lgt * SLICE + (tid & 127) * 4;
        }
        lslot ^= 1;
    };

    if (n > 0) issue_load();                           // prologue: chunk 0

    // ---- compute state (incremental) ----
    int cgt  = c0 >> 9;
    int crow = (c0 & (CHUNKS_PER_GT - 1)) * CHUNK_ROWS;
    float* optrT = out + (size_t)crow * ROWSTRIDE
                       + (cgt * GTILE + gl) * HDIM + hq * 2;
    int cslot = 0;
    int need_w = 1;
    unsigned long long w2[WSZ / 2][2];

    for (int k = 0; k < n; ++k) {
        if (need_w) {                                  // rare: start + <=1 crossing
            need_w = 0;
            const float* wg = W + (size_t)(cgt * GTILE + gl) * (WSZ * HDIM) + hq * 2;
#pragma unroll
            for (int k2 = 0; k2 < WSZ / 2; ++k2) {
                float2 a = *(const float2*)(wg + (2 * k2)     * HDIM);
                float2 b = *(const float2*)(wg + (2 * k2 + 1) * HDIM);
                w2[k2][0] = pack2(a.x, b.x);
                w2[k2][1] = pack2(a.y, b.y);
            }
        }

        asm volatile("cp.async.wait_group 0;");        // chunk k resident
        __syncthreads();   // also: all reads of the other slot (iter k-1) done

        if (k + 1 < n) issue_load();                   // prefetch k+1, other slot

        const float* xb = xs + cslot * (CHUNK_ROWS * SLICE) + gl * WSZ;
#pragma unroll
        for (int rl = 0; rl < CHUNK_ROWS; ++rl) {
            const ulonglong2* xq = (const ulonglong2*)(xb + rl * SLICE);
            ulonglong2 q0 = xq[0], q1 = xq[1], q2 = xq[2], q3 = xq[3];
            unsigned long long a0 = 0ull, a1 = 0ull;
            ffma2(a0, q0.x, w2[0][0]); ffma2(a1, q0.x, w2[0][1]);
            ffma2(a0, q0.y, w2[1][0]); ffma2(a1, q0.y, w2[1][1]);
            ffma2(a0, q1.x, w2[2][0]); ffma2(a1, q1.x, w2[2][1]);
            ffma2(a0, q1.y, w2[3][0]); ffma2(a1, q1.y, w2[3][1]);
            ffma2(a0, q2.x, w2[4][0]); ffma2(a1, q2.x, w2[4][1]);
            ffma2(a0, q2.y, w2[5][0]); ffma2(a1, q2.y, w2[5][1]);
            ffma2(a0, q3.x, w2[6][0]); ffma2(a1, q3.x, w2[6][1]);
            ffma2(a0, q3.y, w2[7][0]); ffma2(a1, q3.y, w2[7][1]);
            float l0, h0, l1, h1;
            unpack2(a0, l0, h0);
            unpack2(a1, l1, h1);
            float2 o;
            o.x = fmaxf(l0 + h0, 0.0f);     // k-pair horizontal reduce + ReLU
            o.y = fmaxf(l1 + h1, 0.0f);
            __stcs((float2*)(optrT + (size_t)rl * ROWSTRIDE), o);  // streaming
        }

        crow  += CHUNK_ROWS;
        optrT += CHUNK_ROWS * ROWSTRIDE;
        if (crow == B_ROWS) {
            crow = 0; ++cgt; need_w = 1;
            optrT = out + (size_t)(cgt * GTILE + gl) * HDIM + hq * 2;
        }
        cslot ^= 1;
    }
}

extern "C" void kernel_launch(void* const* d_in, const int* in_sizes, int n_in,
                              void* d_out, int out_size) {
    const float* x = (const float*)d_in[0];   // (8192, 16384) f32
    const float* W = (const float*)d_in[1];   // (1024, 16, 16) f32
    float* out = (float*)d_out;               // (8192, 16384) f32

    cudaFuncSetAttribute(bd_kernel,
                         cudaFuncAttributeMaxDynamicSharedMemorySize, SMEM_BYTES);

    int sms = 148;
    cudaDeviceGetAttribute(&sms, cudaDevAttrMultiProcessorCount, 0);
    dim3 grid(sms * 3);                        // exactly one wave at occ=3
    bd_kernel<<<grid, BLOCK, SMEM_BYTES>>>(x, W, out);
}